// round 13
// baseline (speedup 1.0000x reference)
#include <cuda_runtime.h>
#include <cuda_bf16.h>
#include <cstdint>

// EdgeDecoder: probs = sigmoid(relu(relu(concat(emb[u],emb[v])@W1+b1)@W2+b2)@W3+b3)
// R10: fully fused tensor-core version (layer1 MMA -> in-register relu/resplit ->
//      layer2 MMA), 3-term bf16 hi/lo splits, raw-emb gather (128B/edge).
// R11: register epilogue (layer3 dot in C-fragment layout + quad shfl reduction).
// R12: multi-tile blocks — 8 tiles of 128 edges per block; weights staged ONCE
//      (weight smem/L2 traffic /8); sU/sV smem staging removed (ei read direct).

#define EPB 128
#define TILES 8
#define APITCH 80        // A row pitch bytes (64B emb-pair data + 16 pad)

// Per-lane packed fragments (prep kernel): W1 [kt1(2)][j(8)][lane], W2 [kt(4)][nt(4)][lane]
__device__ __align__(16) uint2 g_W1fragHi[512];
__device__ __align__(16) uint2 g_W1fragLo[512];
__device__ __align__(16) uint2 g_W2fragHi[512];
__device__ __align__(16) uint2 g_W2fragLo[512];

__device__ __forceinline__ uint32_t smem_u32(const void* p) {
    uint32_t a;
    asm("{ .reg .u64 t; cvta.to.shared.u64 t, %1; cvt.u32.u64 %0, t; }" : "=r"(a) : "l"(p));
    return a;
}
__device__ __forceinline__ void ldmatrix_x4(uint32_t& a0, uint32_t& a1,
                                            uint32_t& a2, uint32_t& a3, uint32_t addr) {
    asm volatile("ldmatrix.sync.aligned.m8n8.x4.shared.b16 {%0,%1,%2,%3}, [%4];"
                 : "=r"(a0), "=r"(a1), "=r"(a2), "=r"(a3) : "r"(addr));
}
__device__ __forceinline__ void mma_bf16(float* c, uint32_t a0, uint32_t a1,
                                         uint32_t a2, uint32_t a3,
                                         uint32_t b0, uint32_t b1) {
    asm volatile("mma.sync.aligned.m16n8k16.row.col.f32.bf16.bf16.f32 "
                 "{%0,%1,%2,%3},{%4,%5,%6,%7},{%8,%9},{%0,%1,%2,%3};"
                 : "+f"(c[0]), "+f"(c[1]), "+f"(c[2]), "+f"(c[3])
                 : "r"(a0), "r"(a1), "r"(a2), "r"(a3), "r"(b0), "r"(b1));
}
__device__ __forceinline__ uint32_t pack_hi(float a, float b) {
    __nv_bfloat162 h = __floats2bfloat162_rn(a, b);
    return *(uint32_t*)&h;
}
__device__ __forceinline__ uint32_t pack_lo(float a, float b, uint32_t hi) {
    __nv_bfloat162 h = *(__nv_bfloat162*)&hi;
    __nv_bfloat162 l = __floats2bfloat162_rn(a - __bfloat162float(h.x),
                                             b - __bfloat162float(h.y));
    return *(uint32_t*)&l;
}

// ---------------- prep: per-lane packed W1/W2 fragments (hi/lo split) ----------------
__global__ void __launch_bounds__(256)
prep_frags(const float* __restrict__ W1, const float* __restrict__ W2) {
    int tid = threadIdx.x;
    for (int e = tid; e < 512; e += 256) {
        int lane = e & 31;
        {   // W1 [32 x 64]: e = kt1*256 + j*32 + lane
            int kt1 = e >> 8, j = (e >> 5) & 7;
            int k0 = kt1 * 16 + (lane & 3) * 2;
            int n  = j * 8 + (lane >> 2);
            float p00 = W1[(k0 + 0) * 64 + n], p01 = W1[(k0 + 1) * 64 + n];
            float p10 = W1[(k0 + 8) * 64 + n], p11 = W1[(k0 + 9) * 64 + n];
            uint32_t h0 = pack_hi(p00, p01), h1 = pack_hi(p10, p11);
            g_W1fragHi[e] = make_uint2(h0, h1);
            g_W1fragLo[e] = make_uint2(pack_lo(p00, p01, h0), pack_lo(p10, p11, h1));
        }
        {   // W2 [64 x 32]: e = kt*128 + nt*32 + lane
            int kt = e >> 7, nt = (e >> 5) & 3;
            int k0 = kt * 16 + (lane & 3) * 2;
            int n  = nt * 8 + (lane >> 2);
            float p00 = W2[(k0 + 0) * 32 + n], p01 = W2[(k0 + 1) * 32 + n];
            float p10 = W2[(k0 + 8) * 32 + n], p11 = W2[(k0 + 9) * 32 + n];
            uint32_t h0 = pack_hi(p00, p01), h1 = pack_hi(p10, p11);
            g_W2fragHi[e] = make_uint2(h0, h1);
            g_W2fragLo[e] = make_uint2(pack_lo(p00, p01, h0), pack_lo(p10, p11, h1));
        }
    }
}

// ---------------- fused edge kernel (multi-tile) ----------------
__global__ void __launch_bounds__(256, 4)
edge_kernel(const float* __restrict__ emb,
            const int* __restrict__ ei,
            const float* __restrict__ b1,
            const float* __restrict__ b2,
            const float* __restrict__ W3,
            const float* __restrict__ b3,
            float* __restrict__ out,
            int E, int do_idx) {
    __shared__ __align__(16) unsigned char sAhi[EPB * APITCH];
    __shared__ __align__(16) unsigned char sAlo[EPB * APITCH];
    __shared__ __align__(16) uint2 sW1H[512], sW1L[512], sW2H[512], sW2L[512];
    __shared__ __align__(16) float sB1[64];
    __shared__ __align__(16) float sB2[32], sW3[32];
    __shared__ float sB3;

    const int tid = threadIdx.x;
    const int wid = tid >> 5, lid = tid & 31;
    const int q = lid & 3;

    // Stage weights/biases ONCE per block.
    for (int i = tid; i < 512; i += 256) {
        sW1H[i] = g_W1fragHi[i]; sW1L[i] = g_W1fragLo[i];
        sW2H[i] = g_W2fragHi[i]; sW2L[i] = g_W2fragLo[i];
    }
    if (tid < 64) sB1[tid] = b1[tid];
    if (tid < 32) { sB2[tid] = b2[tid]; sW3[tid] = W3[tid]; }
    if (tid == 0) sB3 = b3[0];
    __syncthreads();

    const int r0 = wid * 16;
    const uint32_t abh = smem_u32(sAhi);
    const uint32_t abl = smem_u32(sAlo);
    const uint32_t rowoff = ((uint32_t)r0 + (uint32_t)(lid & 15)) * APITCH + ((uint32_t)(lid >> 4)) * 16;

    for (int tile = 0; tile < TILES; tile++) {
        const int base = (blockIdx.x * TILES + tile) * EPB;
        if (base >= E) break;
        const int nE = min(EPB, E - base);

        // Gather raw embeddings: 4 lanes per node row (64B). Node ids read direct
        // from ei (broadcast within quads, L2-hot). Split to bf16 hi/lo.
#pragma unroll
        for (int i = 0; i < 4; i++) {
            int idx = i * 256 + tid;
            int le = idx >> 3;
            int which = (idx >> 2) & 1;
            int s = idx & 3;
            int node = 0;
            if (le < nE) node = __ldg(ei + (size_t)which * E + base + le);
            float4 v = __ldg((const float4*)(emb + (size_t)node * 16) + s);
            uint32_t h01 = pack_hi(v.x, v.y), h23 = pack_hi(v.z, v.w);
            uint32_t l01 = pack_lo(v.x, v.y, h01), l23 = pack_lo(v.z, v.w, h23);
            uint32_t off = (uint32_t)le * APITCH + (uint32_t)which * 32 + (uint32_t)s * 8;
            *(uint2*)(sAhi + off) = make_uint2(h01, h23);
            *(uint2*)(sAlo + off) = make_uint2(l01, l23);
        }
        __syncthreads();

        // Load emb A fragments (2 k-tiles, hi+lo). Warp computes rows [r0, r0+16).
        uint32_t eh[2][4], el[2][4];
        ldmatrix_x4(eh[0][0], eh[0][1], eh[0][2], eh[0][3], abh + rowoff);
        ldmatrix_x4(eh[1][0], eh[1][1], eh[1][2], eh[1][3], abh + rowoff + 32);
        ldmatrix_x4(el[0][0], el[0][1], el[0][2], el[0][3], abl + rowoff);
        ldmatrix_x4(el[1][0], el[1][1], el[1][2], el[1][3], abl + rowoff + 32);

        float acc2[4][4];
#pragma unroll
        for (int nt = 0; nt < 4; nt++)
#pragma unroll
            for (int r = 0; r < 4; r++) acc2[nt][r] = 0.0f;

#pragma unroll
        for (int t = 0; t < 4; t++) {
            // ---- layer1: n-tiles j = 2t, 2t+1 (K=32, 3-term split) ----
            float a1[4] = {0, 0, 0, 0}, a1b[4] = {0, 0, 0, 0};
            {
                int j = 2 * t;
                uint2 w0h = sW1H[j * 32 + lid],  w1h = sW1H[(8 + j) * 32 + lid];
                uint2 w0l = sW1L[j * 32 + lid],  w1l = sW1L[(8 + j) * 32 + lid];
                mma_bf16(a1, eh[0][0], eh[0][1], eh[0][2], eh[0][3], w0h.x, w0h.y);
                mma_bf16(a1, eh[1][0], eh[1][1], eh[1][2], eh[1][3], w1h.x, w1h.y);
                mma_bf16(a1, el[0][0], el[0][1], el[0][2], el[0][3], w0h.x, w0h.y);
                mma_bf16(a1, el[1][0], el[1][1], el[1][2], el[1][3], w1h.x, w1h.y);
                mma_bf16(a1, eh[0][0], eh[0][1], eh[0][2], eh[0][3], w0l.x, w0l.y);
                mma_bf16(a1, eh[1][0], eh[1][1], eh[1][2], eh[1][3], w1l.x, w1l.y);
            }
            {
                int j = 2 * t + 1;
                uint2 w0h = sW1H[j * 32 + lid],  w1h = sW1H[(8 + j) * 32 + lid];
                uint2 w0l = sW1L[j * 32 + lid],  w1l = sW1L[(8 + j) * 32 + lid];
                mma_bf16(a1b, eh[0][0], eh[0][1], eh[0][2], eh[0][3], w0h.x, w0h.y);
                mma_bf16(a1b, eh[1][0], eh[1][1], eh[1][2], eh[1][3], w1h.x, w1h.y);
                mma_bf16(a1b, el[0][0], el[0][1], el[0][2], el[0][3], w0h.x, w0h.y);
                mma_bf16(a1b, el[1][0], el[1][1], el[1][2], el[1][3], w1h.x, w1h.y);
                mma_bf16(a1b, eh[0][0], eh[0][1], eh[0][2], eh[0][3], w0l.x, w0l.y);
                mma_bf16(a1b, eh[1][0], eh[1][1], eh[1][2], eh[1][3], w1l.x, w1l.y);
            }

            // ---- bias + ReLU + re-split: layer1 C-frag == layer2 A-frag (k-tile t) ----
            int col0 = 16 * t + 2 * q;
            float2 ba = *(const float2*)(sB1 + col0);
            float2 bb = *(const float2*)(sB1 + col0 + 8);
            float h0 = fmaxf(a1[0]  + ba.x, 0.0f), h1 = fmaxf(a1[1]  + ba.y, 0.0f);
            float h2 = fmaxf(a1[2]  + ba.x, 0.0f), h3 = fmaxf(a1[3]  + ba.y, 0.0f);
            float g0 = fmaxf(a1b[0] + bb.x, 0.0f), g1 = fmaxf(a1b[1] + bb.y, 0.0f);
            float g2 = fmaxf(a1b[2] + bb.x, 0.0f), g3 = fmaxf(a1b[3] + bb.y, 0.0f);
            uint32_t a0h = pack_hi(h0, h1), a1h_ = pack_hi(h2, h3);
            uint32_t a2h = pack_hi(g0, g1), a3h = pack_hi(g2, g3);
            uint32_t a0l = pack_lo(h0, h1, a0h), a1l = pack_lo(h2, h3, a1h_);
            uint32_t a2l = pack_lo(g0, g1, a2h), a3l = pack_lo(g2, g3, a3h);

            // ---- layer2: accumulate k-tile t into all 4 n-tiles (3-term split) ----
#pragma unroll
            for (int nt = 0; nt < 4; nt++) {
                uint2 bh = sW2H[(t * 4 + nt) * 32 + lid];
                uint2 bl = sW2L[(t * 4 + nt) * 32 + lid];
                mma_bf16(acc2[nt], a0h, a1h_, a2h, a3h, bh.x, bh.y);
                mma_bf16(acc2[nt], a0l, a1l,  a2l, a3l, bh.x, bh.y);
                mma_bf16(acc2[nt], a0h, a1h_, a2h, a3h, bl.x, bl.y);
            }
        }

        // ---- register epilogue: layer3 dot in C-frag layout + quad reduction ----
        float zA = 0.0f, zB = 0.0f;
#pragma unroll
        for (int nt = 0; nt < 4; nt++) {
            float2 bb = *(const float2*)(sB2 + nt * 8 + 2 * q);
            float2 ww = *(const float2*)(sW3 + nt * 8 + 2 * q);
            zA = fmaf(fmaxf(acc2[nt][0] + bb.x, 0.0f), ww.x, zA);
            zA = fmaf(fmaxf(acc2[nt][1] + bb.y, 0.0f), ww.y, zA);
            zB = fmaf(fmaxf(acc2[nt][2] + bb.x, 0.0f), ww.x, zB);
            zB = fmaf(fmaxf(acc2[nt][3] + bb.y, 0.0f), ww.y, zB);
        }
        zA += __shfl_xor_sync(0xffffffffu, zA, 1);
        zA += __shfl_xor_sync(0xffffffffu, zA, 2);
        zB += __shfl_xor_sync(0xffffffffu, zB, 1);
        zB += __shfl_xor_sync(0xffffffffu, zB, 2);
        if (q == 0) {
            int rA = r0 + (lid >> 2);
            int rB = rA + 8;
            if (rA < nE) out[base + rA] = 1.0f / (1.0f + __expf(-(zA + sB3)));
            if (rB < nE) out[base + rB] = 1.0f / (1.0f + __expf(-(zB + sB3)));
        }

        // ---- edge_index passthrough (coalesced direct reads) ----
        if (do_idx) {
            if (tid < EPB) {
                if (tid < nE) out[(size_t)E + base + tid] = (float)__ldg(ei + base + tid);
            } else {
                int t2 = tid - EPB;
                if (t2 < nE) out[(size_t)2 * E + base + t2] = (float)__ldg(ei + (size_t)E + base + t2);
            }
        }
        __syncthreads();   // A smem consumed; safe to overwrite next tile
    }
}

extern "C" void kernel_launch(void* const* d_in, const int* in_sizes, int n_in,
                              void* d_out, int out_size) {
    const float* emb = (const float*)d_in[0];
    const int*   ei  = (const int*)d_in[1];
    const float* W1  = (const float*)d_in[2];
    const float* b1  = (const float*)d_in[3];
    const float* W2  = (const float*)d_in[4];
    const float* b2  = (const float*)d_in[5];
    const float* W3  = (const float*)d_in[6];
    const float* b3  = (const float*)d_in[7];

    int E      = in_sizes[1] / 2;
    float* out = (float*)d_out;
    int do_idx = (out_size >= 3 * E) ? 1 : 0;

    prep_frags<<<1, 256>>>(W1, W2);
    int blocks = (E + EPB * TILES - 1) / (EPB * TILES);
    edge_kernel<<<blocks, 256>>>(emb, ei, b1, b2, W3, b3, out, E, do_idx);
}